// round 7
// baseline (speedup 1.0000x reference)
#include <cuda_runtime.h>
#include <cstdint>

// ============================================================
// Problem sizes
// ============================================================
#define M_TOTAL 8192
#define N_TOTAL 4096
#define K_TOTAL 4096

#define MT 128
#define NT 256
#define KC 32                         // one 32-wide mask block per chunk
#define NUM_CHUNKS (K_TOTAL / KC)     // 128
#define THREADS 256                   // 8 warps: 2 (M) x 4 (N), warp tile 64x64
#define STAGES 4

#define NUM_PID_M (M_TOTAL / MT)      // 64
#define NUM_PID_N (N_TOTAL / NT)      // 16
#define GROUP_M 8

// smem rows: 32 fp32 = 128B data + 16B pad => conflict-free ldmatrix
#define ROWB 144
#define SZ_A (MT * ROWB)                     // 18432
#define SZ_B (NT * ROWB)                     // 36864
#define OFF_A 0
#define OFF_B SZ_A
#define STAGE_BYTES (SZ_A + SZ_B)            // 55296
#define SMEM_BYTES (STAGES * STAGE_BYTES)    // 221184

// sigmoid(s) > 0.1  <=>  s > logit(0.1)
#define SCORE_THRESH (-2.19722457733621938f)

// ============================================================
// Scratch: tf32-prerounded copies of x and W (no allocation)
// ============================================================
__device__ float g_xt[(size_t)M_TOTAL * K_TOTAL];
__device__ float g_wt[(size_t)N_TOTAL * K_TOTAL];

// ============================================================
// PTX helpers (all legal on plain compute_103 target)
// ============================================================
__device__ __forceinline__ uint32_t smem_u32(const void* p) {
    uint32_t a;
    asm("{ .reg .u64 t; cvta.to.shared.u64 t, %1; cvt.u32.u64 %0, t; }" : "=r"(a) : "l"(p));
    return a;
}

__device__ __forceinline__ void cp16(uint32_t dst, const void* src) {
    asm volatile("cp.async.cg.shared.global [%0], [%1], 16;"
                 :: "r"(dst), "l"(src));
}

#define CP_COMMIT() asm volatile("cp.async.commit_group;" ::: "memory")
#define CP_WAIT(n)  asm volatile("cp.async.wait_group %0;" :: "n"(n) : "memory")

__device__ __forceinline__ void ldsm4(uint32_t* r, uint32_t addr) {
    asm volatile("ldmatrix.sync.aligned.m8n8.x4.shared.b16 {%0,%1,%2,%3}, [%4];"
                 : "=r"(r[0]), "=r"(r[1]), "=r"(r[2]), "=r"(r[3]) : "r"(addr));
}

__device__ __forceinline__ float to_tf32f(float f) {
    uint32_t r;
    asm("cvt.rna.tf32.f32 %0, %1;" : "=r"(r) : "f"(f));
    return __uint_as_float(r);
}

__device__ __forceinline__ void mma_tf32(float* c, const uint32_t* a, const uint32_t* b) {
    asm volatile(
        "mma.sync.aligned.m16n8k8.row.col.f32.tf32.tf32.f32 "
        "{%0,%1,%2,%3}, {%4,%5,%6,%7}, {%8,%9}, {%0,%1,%2,%3};"
        : "+f"(c[0]), "+f"(c[1]), "+f"(c[2]), "+f"(c[3])
        : "r"(a[0]), "r"(a[1]), "r"(a[2]), "r"(a[3]), "r"(b[0]), "r"(b[1]));
}

// ============================================================
// Prepass: round fp32 -> tf32 (RNA), store as fp32 bit pattern
// ============================================================
__global__ void __launch_bounds__(256) cvt_tf32_kernel(const float4* __restrict__ src,
                                                       float4* __restrict__ dst,
                                                       unsigned n4) {
    unsigned i = blockIdx.x * blockDim.x + threadIdx.x;
    if (i >= n4) return;
    float4 v = src[i];
    v.x = to_tf32f(v.x);
    v.y = to_tf32f(v.y);
    v.z = to_tf32f(v.z);
    v.w = to_tf32f(v.w);
    dst[i] = v;
}

// ============================================================
// Block-masked GEMM: out = x @ (W.masked)^T + bias
// tf32 single pass (inputs pre-rounded), fp32 accumulate
// 8 warps, warp tile 64x64 (crossbar-traffic-minimal)
// ============================================================
__global__ void __launch_bounds__(THREADS, 1)
gemm_kernel(const float* __restrict__ bias, const float* __restrict__ scores,
            float* __restrict__ out) {
    extern __shared__ char smem[];
    __shared__ unsigned char smask[8][NUM_CHUNKS];   // [local n-block][k-block]

    const int tid = threadIdx.x;
    const int lane = tid & 31;
    const int wid = tid >> 5;        // 8 warps
    const int wm = wid >> 2;         // 2 warp rows (M: 64 each)
    const int wn = wid & 3;          // 4 warp cols (N: 64 each)

    // grouped tile mapping for L2 reuse
    int pid = blockIdx.x;
    int group = pid / (GROUP_M * NUM_PID_N);
    int rem = pid % (GROUP_M * NUM_PID_N);
    int pm = group * GROUP_M + (rem % GROUP_M);
    int pn = rem / GROUP_M;
    const int m0 = pm * MT;
    const int n0 = pn * NT;

    // per-CTA block mask (compare in logit space; identical predicate)
    for (int i = tid; i < 8 * NUM_CHUNKS; i += THREADS) {
        int nb = i >> 7;
        int kb = i & (NUM_CHUNKS - 1);
        smask[nb][kb] = scores[((n0 >> 5) + nb) * (K_TOTAL / 32) + kb] > SCORE_THRESH;
    }
    __syncthreads();

    const uint32_t sbase = smem_u32(smem);

    // ---- loader: one chunk (KC=32 fp32 = 128B per row) into a stage ----
    // Masked B blocks: cp.async NOT issued (their MMAs are skipped, so the
    // stale smem contents are never read) -- saves smem write bandwidth.
    auto load_chunk = [&](int kt, int stg) {
        const uint32_t st = sbase + stg * STAGE_BYTES;
        const int k0 = kt * KC;
        // A: 128 rows x 8 segs of 16B -> 4 ops/thread
#pragma unroll
        for (int i = 0; i < 4; ++i) {
            int op = tid + i * THREADS;
            int row = op >> 3, seg = op & 7;
            const float* g = g_xt + (size_t)(m0 + row) * K_TOTAL + k0 + seg * 4;
            cp16(st + OFF_A + row * ROWB + seg * 16, g);
        }
        // B: 256 rows x 8 segs -> 8 ops/thread, masked rows skipped entirely
#pragma unroll
        for (int i = 0; i < 8; ++i) {
            int op = tid + i * THREADS;
            int row = op >> 3, seg = op & 7;
            if (smask[row >> 5][kt]) {
                const float* g = g_wt + (size_t)(n0 + row) * K_TOTAL + k0 + seg * 4;
                cp16(st + OFF_B + row * ROWB + seg * 16, g);
            }
        }
    };

    float acc[4][8][4];
#pragma unroll
    for (int a = 0; a < 4; ++a)
#pragma unroll
        for (int b = 0; b < 8; ++b)
#pragma unroll
            for (int c = 0; c < 4; ++c) acc[a][b][c] = 0.0f;

    // prologue: fill stages 0..STAGES-2
#pragma unroll
    for (int s = 0; s < STAGES - 1; ++s) {
        load_chunk(s, s);
        CP_COMMIT();
    }

    const int a_lane_row = lane & 15;
    const int a_lane_kb = (lane >> 4) * 16;
    const int b_lane_row = ((lane >> 4) & 1) * 8 + (lane & 7);
    const int b_lane_kb = ((lane >> 3) & 1) * 16;

    for (int kt = 0; kt < NUM_CHUNKS; ++kt) {
        CP_WAIT(STAGES - 2);       // stage kt complete
        __syncthreads();           // everyone done reading stage (kt-1)

        // issue next chunk's loads into the stage read last iteration
        if (kt + STAGES - 1 < NUM_CHUNKS)
            load_chunk(kt + STAGES - 1, (kt + STAGES - 1) % STAGES);
        CP_COMMIT();

        const int stg = kt % STAGES;
        const uint32_t st = sbase + stg * STAGE_BYTES;
        const unsigned g0 = smask[wn * 2 + 0][kt];
        const unsigned g1 = smask[wn * 2 + 1][kt];

        if (g0 | g1) {
#pragma unroll
            for (int ks = 0; ks < 4; ++ks) {        // four k8 steps per chunk
                uint32_t af[4][4];
#pragma unroll
                for (int mf = 0; mf < 4; ++mf) {
                    uint32_t ao = st + OFF_A
                                + (wm * 64 + mf * 16 + a_lane_row) * ROWB
                                + a_lane_kb + ks * 32;
                    ldsm4(af[mf], ao);
                }
#pragma unroll
                for (int p = 0; p < 4; ++p) {       // 4 groups of 16 N rows
                    if (((p < 2) ? g0 : g1) == 0) continue;
                    uint32_t bo = st + OFF_B
                                + (wn * 64 + p * 16 + b_lane_row) * ROWB
                                + b_lane_kb + ks * 32;
                    uint32_t bf[4];
                    ldsm4(bf, bo);
#pragma unroll
                    for (int mf = 0; mf < 4; ++mf) {
                        mma_tf32(acc[mf][p * 2 + 0], af[mf], &bf[0]);   // n rows 0-7
                        mma_tf32(acc[mf][p * 2 + 1], af[mf], &bf[2]);   // n rows 8-15
                    }
                }
            }
        }
    }

    // ---- epilogue: bias + fp32 stores ----
    const int er = lane >> 2;            // 0..7
    const int ec = (lane & 3) * 2;       // 0,2,4,6
#pragma unroll
    for (int mf = 0; mf < 4; ++mf) {
#pragma unroll
        for (int nf = 0; nf < 8; ++nf) {
            int col = n0 + wn * 64 + nf * 8 + ec;
            float b0 = bias[col];
            float b1 = bias[col + 1];
            int r0 = m0 + wm * 64 + mf * 16 + er;
            float2 v0 = make_float2(acc[mf][nf][0] + b0, acc[mf][nf][1] + b1);
            float2 v1 = make_float2(acc[mf][nf][2] + b0, acc[mf][nf][3] + b1);
            *reinterpret_cast<float2*>(&out[(size_t)r0 * N_TOTAL + col]) = v0;
            *reinterpret_cast<float2*>(&out[(size_t)(r0 + 8) * N_TOTAL + col]) = v1;
        }
    }
}

// ============================================================
// kernel_launch
// ============================================================
extern "C" void kernel_launch(void* const* d_in, const int* in_sizes, int n_in,
                              void* d_out, int out_size) {
    const float* x      = (const float*)d_in[0];  // [8192, 4096]
    const float* weight = (const float*)d_in[1];  // [4096, 4096]
    const float* bias   = (const float*)d_in[2];  // [4096]
    const float* scores = (const float*)d_in[3];  // [128, 128]
    float* out = (float*)d_out;                   // [8192, 4096]
    (void)in_sizes; (void)n_in; (void)out_size;

    float *xt, *wt;
    cudaGetSymbolAddress((void**)&xt, g_xt);
    cudaGetSymbolAddress((void**)&wt, g_wt);

    {
        unsigned n4 = (unsigned)((size_t)M_TOTAL * K_TOTAL / 4);
        cvt_tf32_kernel<<<(n4 + 255) / 256, 256>>>((const float4*)x, (float4*)xt, n4);
    }
    {
        unsigned n4 = (unsigned)((size_t)N_TOTAL * K_TOTAL / 4);
        cvt_tf32_kernel<<<(n4 + 255) / 256, 256>>>((const float4*)weight, (float4*)wt, n4);
    }

    cudaFuncSetAttribute(gemm_kernel, cudaFuncAttributeMaxDynamicSharedMemorySize,
                         SMEM_BYTES);
    gemm_kernel<<<NUM_PID_M * NUM_PID_N, THREADS, SMEM_BYTES>>>(bias, scores, out);
}

// round 8
// speedup vs baseline: 1.1445x; 1.1445x over previous
#include <cuda_runtime.h>
#include <cstdint>

// ============================================================
// Problem sizes
// ============================================================
#define M_TOTAL 8192
#define N_TOTAL 4096
#define K_TOTAL 4096

#define MT 128
#define NT 128
#define KC 32                         // one 32-wide mask block per chunk
#define NUM_CHUNKS (K_TOTAL / KC)     // 128
#define THREADS 256                   // 8 warps: 2 (M) x 4 (N), warp tile 64x32
#define STAGES 3

#define NUM_PID_M (M_TOTAL / MT)      // 64
#define NUM_PID_N (N_TOTAL / NT)      // 32
#define GROUP_M 8

// smem rows: 32 fp32 = 128B data + 16B pad => conflict-free ldmatrix
#define ROWB 144
#define SZ_A (MT * ROWB)                     // 18432
#define SZ_B (NT * ROWB)                     // 18432
#define OFF_A 0
#define OFF_B SZ_A
#define STAGE_BYTES (SZ_A + SZ_B)            // 36864
#define SMEM_BYTES (STAGES * STAGE_BYTES)    // 110592 -> 2 CTAs/SM

// sigmoid(s) > 0.1  <=>  s > logit(0.1)
#define SCORE_THRESH (-2.19722457733621938f)

// ============================================================
// Scratch: tf32-prerounded copies of x and W (no allocation)
// ============================================================
__device__ float g_xt[(size_t)M_TOTAL * K_TOTAL];
__device__ float g_wt[(size_t)N_TOTAL * K_TOTAL];

// ============================================================
// PTX helpers (all legal on plain compute_103 target)
// ============================================================
__device__ __forceinline__ uint32_t smem_u32(const void* p) {
    uint32_t a;
    asm("{ .reg .u64 t; cvta.to.shared.u64 t, %1; cvt.u32.u64 %0, t; }" : "=r"(a) : "l"(p));
    return a;
}

__device__ __forceinline__ void cp16(uint32_t dst, const void* src) {
    asm volatile("cp.async.cg.shared.global [%0], [%1], 16;"
                 :: "r"(dst), "l"(src));
}

#define CP_COMMIT() asm volatile("cp.async.commit_group;" ::: "memory")
#define CP_WAIT(n)  asm volatile("cp.async.wait_group %0;" :: "n"(n) : "memory")

__device__ __forceinline__ void ldsm4(uint32_t* r, uint32_t addr) {
    asm volatile("ldmatrix.sync.aligned.m8n8.x4.shared.b16 {%0,%1,%2,%3}, [%4];"
                 : "=r"(r[0]), "=r"(r[1]), "=r"(r[2]), "=r"(r[3]) : "r"(addr));
}

__device__ __forceinline__ float to_tf32f(float f) {
    uint32_t r;
    asm("cvt.rna.tf32.f32 %0, %1;" : "=r"(r) : "f"(f));
    return __uint_as_float(r);
}

__device__ __forceinline__ void mma_tf32(float* c, const uint32_t* a, const uint32_t* b) {
    asm volatile(
        "mma.sync.aligned.m16n8k8.row.col.f32.tf32.tf32.f32 "
        "{%0,%1,%2,%3}, {%4,%5,%6,%7}, {%8,%9}, {%0,%1,%2,%3};"
        : "+f"(c[0]), "+f"(c[1]), "+f"(c[2]), "+f"(c[3])
        : "r"(a[0]), "r"(a[1]), "r"(a[2]), "r"(a[3]), "r"(b[0]), "r"(b[1]));
}

// ============================================================
// Prepass: round fp32 -> tf32 (RNA), store as fp32 bit pattern
// ============================================================
__global__ void __launch_bounds__(256) cvt_tf32_kernel(const float4* __restrict__ src,
                                                       float4* __restrict__ dst,
                                                       unsigned n4) {
    unsigned i = blockIdx.x * blockDim.x + threadIdx.x;
    if (i >= n4) return;
    float4 v = src[i];
    v.x = to_tf32f(v.x);
    v.y = to_tf32f(v.y);
    v.z = to_tf32f(v.z);
    v.w = to_tf32f(v.w);
    dst[i] = v;
}

// ============================================================
// Block-masked GEMM: out = x @ (W.masked)^T + bias
// tf32 single pass (inputs pre-rounded), fp32 accumulate
// 8 warps (64x32 tiles), 2 CTAs/SM for latency hiding
// ============================================================
__global__ void __launch_bounds__(THREADS, 2)
gemm_kernel(const float* __restrict__ bias, const float* __restrict__ scores,
            float* __restrict__ out) {
    extern __shared__ char smem[];
    __shared__ unsigned char smask[NT / 32][NUM_CHUNKS];   // [local n-block][k-block]

    const int tid = threadIdx.x;
    const int lane = tid & 31;
    const int wid = tid >> 5;        // 8 warps
    const int wm = wid >> 2;         // 2 warp rows (M: 64 each)
    const int wn = wid & 3;          // 4 warp cols (N: 32 each) = 1 mask block

    // grouped tile mapping for L2 reuse
    int pid = blockIdx.x;
    int group = pid / (GROUP_M * NUM_PID_N);
    int rem = pid % (GROUP_M * NUM_PID_N);
    int pm = group * GROUP_M + (rem % GROUP_M);
    int pn = rem / GROUP_M;
    const int m0 = pm * MT;
    const int n0 = pn * NT;

    // per-CTA block mask (compare in logit space; identical predicate)
    for (int i = tid; i < (NT / 32) * NUM_CHUNKS; i += THREADS) {
        int nb = i >> 7;
        int kb = i & (NUM_CHUNKS - 1);
        smask[nb][kb] = scores[((n0 >> 5) + nb) * (K_TOTAL / 32) + kb] > SCORE_THRESH;
    }
    __syncthreads();

    const uint32_t sbase = smem_u32(smem);

    // ---- loader: one chunk (KC=32 fp32 = 128B per row) into a stage ----
    // Masked B blocks: cp.async not issued (their MMAs are skipped).
    auto load_chunk = [&](int kt, int stg) {
        const uint32_t st = sbase + stg * STAGE_BYTES;
        const int k0 = kt * KC;
        // A: 128 rows x 8 segs of 16B -> 4 ops/thread
#pragma unroll
        for (int i = 0; i < 4; ++i) {
            int op = tid + i * THREADS;
            int row = op >> 3, seg = op & 7;
            const float* g = g_xt + (size_t)(m0 + row) * K_TOTAL + k0 + seg * 4;
            cp16(st + OFF_A + row * ROWB + seg * 16, g);
        }
        // B: 128 rows x 8 segs -> 4 ops/thread, masked rows skipped entirely
#pragma unroll
        for (int i = 0; i < 4; ++i) {
            int op = tid + i * THREADS;
            int row = op >> 3, seg = op & 7;
            if (smask[row >> 5][kt]) {
                const float* g = g_wt + (size_t)(n0 + row) * K_TOTAL + k0 + seg * 4;
                cp16(st + OFF_B + row * ROWB + seg * 16, g);
            }
        }
    };

    float acc[4][4][4];
#pragma unroll
    for (int a = 0; a < 4; ++a)
#pragma unroll
        for (int b = 0; b < 4; ++b)
#pragma unroll
            for (int c = 0; c < 4; ++c) acc[a][b][c] = 0.0f;

    // prologue: fill stages 0..STAGES-2
#pragma unroll
    for (int s = 0; s < STAGES - 1; ++s) {
        load_chunk(s, s);
        CP_COMMIT();
    }

    const int a_lane_row = lane & 15;
    const int a_lane_kb = (lane >> 4) * 16;
    const int b_lane_row = ((lane >> 4) & 1) * 8 + (lane & 7);
    const int b_lane_kb = ((lane >> 3) & 1) * 16;

    for (int kt = 0; kt < NUM_CHUNKS; ++kt) {
        CP_WAIT(STAGES - 2);       // stage kt complete
        __syncthreads();           // everyone done reading stage (kt-1)

        // issue next chunk's loads into the stage read last iteration
        if (kt + STAGES - 1 < NUM_CHUNKS)
            load_chunk(kt + STAGES - 1, (kt + STAGES - 1) % STAGES);
        CP_COMMIT();

        // whole-chunk skip: this warp's single 32-wide n-block
        if (!smask[wn][kt]) continue;

        const int stg = kt % STAGES;
        const uint32_t st = sbase + stg * STAGE_BYTES;

#pragma unroll
        for (int ks = 0; ks < 4; ++ks) {        // four k8 steps per chunk
            uint32_t af[4][4];
#pragma unroll
            for (int mf = 0; mf < 4; ++mf) {
                uint32_t ao = st + OFF_A
                            + (wm * 64 + mf * 16 + a_lane_row) * ROWB
                            + a_lane_kb + ks * 32;
                ldsm4(af[mf], ao);
            }
#pragma unroll
            for (int p = 0; p < 2; ++p) {       // 2 groups of 16 N rows
                uint32_t bo = st + OFF_B
                            + (wn * 32 + p * 16 + b_lane_row) * ROWB
                            + b_lane_kb + ks * 32;
                uint32_t bf[4];
                ldsm4(bf, bo);
#pragma unroll
                for (int mf = 0; mf < 4; ++mf) {
                    mma_tf32(acc[mf][p * 2 + 0], af[mf], &bf[0]);   // n rows 0-7
                    mma_tf32(acc[mf][p * 2 + 1], af[mf], &bf[2]);   // n rows 8-15
                }
            }
        }
    }

    // ---- epilogue: bias + fp32 stores ----
    const int er = lane >> 2;            // 0..7
    const int ec = (lane & 3) * 2;       // 0,2,4,6
#pragma unroll
    for (int mf = 0; mf < 4; ++mf) {
#pragma unroll
        for (int nf = 0; nf < 4; ++nf) {
            int col = n0 + wn * 32 + nf * 8 + ec;
            float b0 = bias[col];
            float b1 = bias[col + 1];
            int r0 = m0 + wm * 64 + mf * 16 + er;
            float2 v0 = make_float2(acc[mf][nf][0] + b0, acc[mf][nf][1] + b1);
            float2 v1 = make_float2(acc[mf][nf][2] + b0, acc[mf][nf][3] + b1);
            *reinterpret_cast<float2*>(&out[(size_t)r0 * N_TOTAL + col]) = v0;
            *reinterpret_cast<float2*>(&out[(size_t)(r0 + 8) * N_TOTAL + col]) = v1;
        }
    }
}

// ============================================================
// kernel_launch
// ============================================================
extern "C" void kernel_launch(void* const* d_in, const int* in_sizes, int n_in,
                              void* d_out, int out_size) {
    const float* x      = (const float*)d_in[0];  // [8192, 4096]
    const float* weight = (const float*)d_in[1];  // [4096, 4096]
    const float* bias   = (const float*)d_in[2];  // [4096]
    const float* scores = (const float*)d_in[3];  // [128, 128]
    float* out = (float*)d_out;                   // [8192, 4096]
    (void)in_sizes; (void)n_in; (void)out_size;

    float *xt, *wt;
    cudaGetSymbolAddress((void**)&xt, g_xt);
    cudaGetSymbolAddress((void**)&wt, g_wt);

    {
        unsigned n4 = (unsigned)((size_t)M_TOTAL * K_TOTAL / 4);
        cvt_tf32_kernel<<<(n4 + 255) / 256, 256>>>((const float4*)x, (float4*)xt, n4);
    }
    {
        unsigned n4 = (unsigned)((size_t)N_TOTAL * K_TOTAL / 4);
        cvt_tf32_kernel<<<(n4 + 255) / 256, 256>>>((const float4*)weight, (float4*)wt, n4);
    }

    cudaFuncSetAttribute(gemm_kernel, cudaFuncAttributeMaxDynamicSharedMemorySize,
                         SMEM_BYTES);
    gemm_kernel<<<NUM_PID_M * NUM_PID_N, THREADS, SMEM_BYTES>>>(bias, scores, out);
}

// round 9
// speedup vs baseline: 2.2565x; 1.9716x over previous
#include <cuda_runtime.h>
#include <cuda_fp16.h>
#include <cstdint>

// ============================================================
// Problem sizes
// ============================================================
#define M_TOTAL 8192
#define N_TOTAL 4096
#define K_TOTAL 4096

#define MT 128
#define NT 128
#define KC 64                         // two 32-wide mask blocks per chunk
#define NUM_CHUNKS (K_TOTAL / KC)     // 64
#define THREADS 256                   // 8 warps: 2 (M) x 4 (N), warp tile 64x32
#define STAGES 3

#define NUM_PID_M (M_TOTAL / MT)      // 64
#define NUM_PID_N (N_TOTAL / NT)      // 32
#define GROUP_M 8

// smem rows: 64 fp16 = 128B data + 16B pad => conflict-free ldmatrix
#define ROWB 144
#define SZ_A (MT * ROWB)                     // 18432
#define SZ_B (NT * ROWB)                     // 18432
#define OFF_A 0
#define OFF_B SZ_A
#define STAGE_BYTES (SZ_A + SZ_B)            // 36864
#define SMEM_BYTES (STAGES * STAGE_BYTES)    // 110592 -> 2 CTAs/SM

// sigmoid(s) > 0.1  <=>  s > logit(0.1)
#define SCORE_THRESH (-2.19722457733621938f)

// ============================================================
// Scratch: fp16 copies of x and W (no allocation)
// ============================================================
__device__ __half g_xh[(size_t)M_TOTAL * K_TOTAL];
__device__ __half g_wh[(size_t)N_TOTAL * K_TOTAL];

// ============================================================
// PTX helpers (all legal on plain compute_103 target)
// ============================================================
__device__ __forceinline__ uint32_t smem_u32(const void* p) {
    uint32_t a;
    asm("{ .reg .u64 t; cvta.to.shared.u64 t, %1; cvt.u32.u64 %0, t; }" : "=r"(a) : "l"(p));
    return a;
}

__device__ __forceinline__ void cp16(uint32_t dst, const void* src) {
    asm volatile("cp.async.cg.shared.global [%0], [%1], 16;"
                 :: "r"(dst), "l"(src));
}

#define CP_COMMIT() asm volatile("cp.async.commit_group;" ::: "memory")
#define CP_WAIT(n)  asm volatile("cp.async.wait_group %0;" :: "n"(n) : "memory")

__device__ __forceinline__ void ldsm4(uint32_t* r, uint32_t addr) {
    asm volatile("ldmatrix.sync.aligned.m8n8.x4.shared.b16 {%0,%1,%2,%3}, [%4];"
                 : "=r"(r[0]), "=r"(r[1]), "=r"(r[2]), "=r"(r[3]) : "r"(addr));
}

__device__ __forceinline__ void mma_f16(float* c, const uint32_t* a, const uint32_t* b) {
    asm volatile(
        "mma.sync.aligned.m16n8k16.row.col.f32.f16.f16.f32 "
        "{%0,%1,%2,%3}, {%4,%5,%6,%7}, {%8,%9}, {%0,%1,%2,%3};"
        : "+f"(c[0]), "+f"(c[1]), "+f"(c[2]), "+f"(c[3])
        : "r"(a[0]), "r"(a[1]), "r"(a[2]), "r"(a[3]), "r"(b[0]), "r"(b[1]));
}

// ============================================================
// Prepass: fp32 -> fp16 (RNE)
// ============================================================
__global__ void __launch_bounds__(256) cvt_f16_kernel(const float4* __restrict__ src,
                                                      __half2* __restrict__ dst,
                                                      unsigned n4) {
    unsigned i = blockIdx.x * blockDim.x + threadIdx.x;
    if (i >= n4) return;
    float4 v = src[i];
    dst[(size_t)i * 2 + 0] = __floats2half2_rn(v.x, v.y);
    dst[(size_t)i * 2 + 1] = __floats2half2_rn(v.z, v.w);
}

// ============================================================
// Block-masked GEMM: out = x @ (W.masked)^T + bias
// fp16 single pass (same 11-bit mantissa as tf32), fp32 accumulate
// 8 warps (64x32 tiles), 2 CTAs/SM, KC=64 (fewer barrier chunks)
// ============================================================
__global__ void __launch_bounds__(THREADS, 2)
gemm_kernel(const float* __restrict__ bias, const float* __restrict__ scores,
            float* __restrict__ out) {
    extern __shared__ char smem[];
    __shared__ unsigned char smask[NT / 32][K_TOTAL / 32];   // [n-block][k-block]

    const int tid = threadIdx.x;
    const int lane = tid & 31;
    const int wid = tid >> 5;        // 8 warps
    const int wm = wid >> 2;         // 2 warp rows (M: 64 each)
    const int wn = wid & 3;          // 4 warp cols (N: 32 each) = 1 mask block

    // grouped tile mapping for L2 reuse
    int pid = blockIdx.x;
    int group = pid / (GROUP_M * NUM_PID_N);
    int rem = pid % (GROUP_M * NUM_PID_N);
    int pm = group * GROUP_M + (rem % GROUP_M);
    int pn = rem / GROUP_M;
    const int m0 = pm * MT;
    const int n0 = pn * NT;

    // per-CTA block mask (compare in logit space; identical predicate)
    for (int i = tid; i < (NT / 32) * (K_TOTAL / 32); i += THREADS) {
        int nb = i >> 7;
        int kb = i & 127;
        smask[nb][kb] = scores[((n0 >> 5) + nb) * (K_TOTAL / 32) + kb] > SCORE_THRESH;
    }
    __syncthreads();

    const uint32_t sbase = smem_u32(smem);

    // ---- loader: one chunk (KC=64 fp16 = 128B per row) into a stage ----
    // Masked B sub-blocks: cp.async not issued (their MMAs are skipped).
    auto load_chunk = [&](int kt, int stg) {
        const uint32_t st = sbase + stg * STAGE_BYTES;
        const int k0 = kt * KC;
        const int kb0 = kt * 2;
        // A: 128 rows x 8 segs of 16B -> 4 ops/thread
#pragma unroll
        for (int i = 0; i < 4; ++i) {
            int op = tid + i * THREADS;
            int row = op >> 3, seg = op & 7;
            const __half* g = g_xh + (size_t)(m0 + row) * K_TOTAL + k0 + seg * 8;
            cp16(st + OFF_A + row * ROWB + seg * 16, g);
        }
        // B: 128 rows x 8 segs -> 4 ops/thread; seg<4 -> k-block kb0, else kb0+1
#pragma unroll
        for (int i = 0; i < 4; ++i) {
            int op = tid + i * THREADS;
            int row = op >> 3, seg = op & 7;
            if (smask[row >> 5][kb0 + (seg >> 2)]) {
                const __half* g = g_wh + (size_t)(n0 + row) * K_TOTAL + k0 + seg * 8;
                cp16(st + OFF_B + row * ROWB + seg * 16, g);
            }
        }
    };

    float acc[4][4][4];
#pragma unroll
    for (int a = 0; a < 4; ++a)
#pragma unroll
        for (int b = 0; b < 4; ++b)
#pragma unroll
            for (int c = 0; c < 4; ++c) acc[a][b][c] = 0.0f;

    // prologue: fill stages 0..STAGES-2
#pragma unroll
    for (int s = 0; s < STAGES - 1; ++s) {
        load_chunk(s, s);
        CP_COMMIT();
    }

    const int a_lane_row = lane & 15;
    const int a_lane_kh = (lane >> 4) * 16;
    const int b_lane_row = ((lane >> 4) & 1) * 8 + (lane & 7);
    const int b_lane_kh = ((lane >> 3) & 1) * 16;

    for (int kt = 0; kt < NUM_CHUNKS; ++kt) {
        CP_WAIT(STAGES - 2);       // stage kt complete
        __syncthreads();           // everyone done reading stage (kt-1)

        // issue next chunk's loads into the stage read last iteration
        if (kt + STAGES - 1 < NUM_CHUNKS)
            load_chunk(kt + STAGES - 1, (kt + STAGES - 1) % STAGES);
        CP_COMMIT();

        // this warp's two 32-wide k-blocks for its single n-block
        const unsigned g0 = smask[wn][kt * 2 + 0];
        const unsigned g1 = smask[wn][kt * 2 + 1];
        if (!(g0 | g1)) continue;

        const int stg = kt % STAGES;
        const uint32_t st = sbase + stg * STAGE_BYTES;

#pragma unroll
        for (int ks = 0; ks < 4; ++ks) {        // four k16 steps per chunk
            if (((ks < 2) ? g0 : g1) == 0) continue;
            uint32_t af[4][4];
#pragma unroll
            for (int mf = 0; mf < 4; ++mf) {
                uint32_t ao = st + OFF_A
                            + (wm * 64 + mf * 16 + a_lane_row) * ROWB
                            + a_lane_kh + ks * 32;
                ldsm4(af[mf], ao);
            }
#pragma unroll
            for (int p = 0; p < 2; ++p) {       // 2 groups of 16 N rows
                uint32_t bo = st + OFF_B
                            + (wn * 32 + p * 16 + b_lane_row) * ROWB
                            + b_lane_kh + ks * 32;
                uint32_t bf[4];
                ldsm4(bf, bo);
#pragma unroll
                for (int mf = 0; mf < 4; ++mf) {
                    mma_f16(acc[mf][p * 2 + 0], af[mf], &bf[0]);   // n rows 0-7
                    mma_f16(acc[mf][p * 2 + 1], af[mf], &bf[2]);   // n rows 8-15
                }
            }
        }
    }

    // ---- epilogue: bias + fp32 stores ----
    const int er = lane >> 2;            // 0..7
    const int ec = (lane & 3) * 2;       // 0,2,4,6
#pragma unroll
    for (int mf = 0; mf < 4; ++mf) {
#pragma unroll
        for (int nf = 0; nf < 4; ++nf) {
            int col = n0 + wn * 32 + nf * 8 + ec;
            float b0 = bias[col];
            float b1 = bias[col + 1];
            int r0 = m0 + wm * 64 + mf * 16 + er;
            float2 v0 = make_float2(acc[mf][nf][0] + b0, acc[mf][nf][1] + b1);
            float2 v1 = make_float2(acc[mf][nf][2] + b0, acc[mf][nf][3] + b1);
            *reinterpret_cast<float2*>(&out[(size_t)r0 * N_TOTAL + col]) = v0;
            *reinterpret_cast<float2*>(&out[(size_t)(r0 + 8) * N_TOTAL + col]) = v1;
        }
    }
}

// ============================================================
// kernel_launch
// ============================================================
extern "C" void kernel_launch(void* const* d_in, const int* in_sizes, int n_in,
                              void* d_out, int out_size) {
    const float* x      = (const float*)d_in[0];  // [8192, 4096]
    const float* weight = (const float*)d_in[1];  // [4096, 4096]
    const float* bias   = (const float*)d_in[2];  // [4096]
    const float* scores = (const float*)d_in[3];  // [128, 128]
    float* out = (float*)d_out;                   // [8192, 4096]
    (void)in_sizes; (void)n_in; (void)out_size;

    __half *xh, *wh;
    cudaGetSymbolAddress((void**)&xh, g_xh);
    cudaGetSymbolAddress((void**)&wh, g_wh);

    {
        unsigned n4 = (unsigned)((size_t)M_TOTAL * K_TOTAL / 4);
        cvt_f16_kernel<<<(n4 + 255) / 256, 256>>>((const float4*)x, (__half2*)xh, n4);
    }
    {
        unsigned n4 = (unsigned)((size_t)N_TOTAL * K_TOTAL / 4);
        cvt_f16_kernel<<<(n4 + 255) / 256, 256>>>((const float4*)weight, (__half2*)wh, n4);
    }

    cudaFuncSetAttribute(gemm_kernel, cudaFuncAttributeMaxDynamicSharedMemorySize,
                         SMEM_BYTES);
    gemm_kernel<<<NUM_PID_M * NUM_PID_N, THREADS, SMEM_BYTES>>>(bias, scores, out);
}